// round 17
// baseline (speedup 1.0000x reference)
#include <cuda_runtime.h>
#include <cuda_fp16.h>
#include <math.h>
#include <stdint.h>

#define Bb 4
#define Ss 4096
#define Dd 1024
#define DI 2048
#define HD 256
#define Mm (Bb * Ss)   // 16384 tokens
#define CL 64          // scan chunk length
#define NC (Ss / CL)   // 64 chunks

// ---------------- scratch (device-code references ONLY; never named in host code) ----
__device__ __half g_xz[(size_t)Mm * 2 * DI];     // 128 MB (gemm1 out, fp16)
__device__ __half g_xnh[(size_t)Mm * Dd];        //  32 MB (LN out, fp16)
__device__ __half g_acth[(size_t)Mm * DI];       //  64 MB (scan out, fp16)
__device__ __half g_w1h[(size_t)2 * DI * Dd];    //   8 MB (in_proj fp16)
__device__ __half g_w2h[(size_t)Dd * DI];        //   4 MB (out_proj fp16)
__device__ float g_e[(size_t)Bb * NC * DI];      //   2 MB (chunk end values)
__device__ float g_s[(size_t)Bb * NC * DI];      //   2 MB (chunk init states)

// ================= helpers =================
__device__ __forceinline__ uint32_t smem_u32(const void* p) {
    uint32_t a;
    asm("{ .reg .u64 t; cvta.to.shared.u64 t, %1; cvt.u32.u64 %0, t; }" : "=r"(a) : "l"(p));
    return a;
}
__device__ __forceinline__ void cp16(uint32_t dst, const void* src) {
    asm volatile("cp.async.cg.shared.global [%0], [%1], 16;" :: "r"(dst), "l"(src));
}
__device__ __forceinline__ void cp_commit() { asm volatile("cp.async.commit_group;" ::: "memory"); }
template <int N> __device__ __forceinline__ void cp_wait() {
    asm volatile("cp.async.wait_group %0;" :: "n"(N) : "memory");
}
__device__ __forceinline__ void ldsm4(uint32_t& r0, uint32_t& r1, uint32_t& r2, uint32_t& r3,
                                      uint32_t addr) {
    asm volatile("ldmatrix.sync.aligned.m8n8.x4.shared.b16 {%0,%1,%2,%3}, [%4];"
                 : "=r"(r0), "=r"(r1), "=r"(r2), "=r"(r3) : "r"(addr));
}
__device__ __forceinline__ void mma_f16(float* d, const uint32_t* a, const uint32_t* b) {
    asm volatile(
        "mma.sync.aligned.m16n8k16.row.col.f32.f16.f16.f32 "
        "{%0,%1,%2,%3}, {%4,%5,%6,%7}, {%8,%9}, {%0,%1,%2,%3};"
        : "+f"(d[0]), "+f"(d[1]), "+f"(d[2]), "+f"(d[3])
        : "r"(a[0]), "r"(a[1]), "r"(a[2]), "r"(a[3]), "r"(b[0]), "r"(b[1]));
}

// ---------------- weight round to fp16 ----------------
template <int WHICH>
__global__ void __launch_bounds__(256) wprep(const float* __restrict__ s) {
    __half* d = (WHICH == 1) ? g_w1h : g_w2h;
    const int n4 = (WHICH == 1) ? (2 * DI * Dd / 4) : (Dd * DI / 4);
    int i = blockIdx.x * 256 + threadIdx.x;
    if (i < n4) {
        float4 v = ((const float4*)s)[i];
        *(__half2*)(d + (size_t)i * 4)     = __halves2half2(__float2half_rn(v.x), __float2half_rn(v.y));
        *(__half2*)(d + (size_t)i * 4 + 2) = __halves2half2(__float2half_rn(v.z), __float2half_rn(v.w));
    }
}

// ---------------- LayerNorm (writes fp16) ----------------
__global__ void __launch_bounds__(256) ln_kernel(const float* __restrict__ x,
                                                 const float* __restrict__ w,
                                                 const float* __restrict__ bia) {
    int m = blockIdx.x;
    int t = threadIdx.x;
    const float4* xr = (const float4*)(x + (size_t)m * Dd);
    float4 xv = xr[t];
    float s  = xv.x + xv.y + xv.z + xv.w;
    float s2 = xv.x * xv.x + xv.y * xv.y + xv.z * xv.z + xv.w * xv.w;
    #pragma unroll
    for (int o = 16; o; o >>= 1) {
        s  += __shfl_xor_sync(0xffffffffu, s, o);
        s2 += __shfl_xor_sync(0xffffffffu, s2, o);
    }
    __shared__ float shs[8], shs2[8];
    int wid = t >> 5, lane = t & 31;
    if (lane == 0) { shs[wid] = s; shs2[wid] = s2; }
    __syncthreads();
    s = 0.f; s2 = 0.f;
    #pragma unroll
    for (int i = 0; i < 8; i++) { s += shs[i]; s2 += shs2[i]; }
    float mu  = s * (1.0f / Dd);
    float var = s2 * (1.0f / Dd) - mu * mu;
    float rstd = rsqrtf(var + 1e-5f);
    float4 wv = ((const float4*)w)[t];
    float4 bv = ((const float4*)bia)[t];
    float o0 = (xv.x - mu) * rstd * wv.x + bv.x;
    float o1 = (xv.y - mu) * rstd * wv.y + bv.y;
    float o2 = (xv.z - mu) * rstd * wv.z + bv.z;
    float o3 = (xv.w - mu) * rstd * wv.w + bv.w;
    size_t base = (size_t)m * Dd + 4 * t;
    *(__half2*)(g_xnh + base)     = __halves2half2(__float2half_rn(o0), __float2half_rn(o1));
    *(__half2*)(g_xnh + base + 2) = __halves2half2(__float2half_rn(o2), __float2half_rn(o3));
}

// ==== fp16 GEMM: CTA 128x128 (256 thr, 8 warps 2m x 4n), warp 64x32, BK=32, 4-stage ====
// 2 CTAs/SM (16 warps). Producers run 2 stages ahead (cp_wait<2>).
// Per stage each plane = 128 rows x 32 halfs (64 B data) at row stride 40 halfs.
// Coverage: 256 threads x 2 cp16 (32 B) per plane = 8192 B  ✓ (round-15 bug: was 1 cp16).
#define HST 40
#define A_PL (128 * HST * 2)               // 10240
#define STG  (2 * A_PL)                    // 20480 (A + B planes)
#define NSTAGE 4
#define GEMM_SMEM (NSTAGE * STG)           // 81920 per CTA

template <int WHICH>                        // 1: xn @ w1 -> g_xz(half) ; 2: act @ w2 + R -> out(f32)
__global__ void __launch_bounds__(256, 2) gemm_h(const float* __restrict__ R,
                                                 float* __restrict__ Cout) {
    constexpr int NTOT = (WHICH == 1) ? 2 * DI : Dd;
    constexpr int KK   = (WHICH == 1) ? Dd : DI;
    const __half* Ap = (WHICH == 1) ? g_xnh : g_acth;
    const __half* Wp = (WHICH == 1) ? g_w1h : g_w2h;

    extern __shared__ char smraw[];
    uint32_t sb = smem_u32(smraw);
    int tid = threadIdx.x, lane = tid & 31, wid = tid >> 5;
    int wm = wid & 1, wn = wid >> 1;               // 2 x 4
    int bm = blockIdx.y * 128, bn = blockIdx.x * 128;
    int lr = lane >> 2, lc = lane & 3;

    // producers: row pr (0..127), half-range pc..pc+15 (pc in halfs: 0 or 16)
    int pr = tid >> 1, pc = (tid & 1) * 16;
    const __half* pA = Ap + (size_t)(bm + pr) * KK + pc;
    const __half* pW = Wp + (size_t)(bn + pr) * KK + pc;
    uint32_t dA = sb + (uint32_t)(pr * HST + pc) * 2;
    uint32_t dW = dA + A_PL;

    const int NIT = KK / 32;
    #define ISSUE(s, k0) do {                          \
        cp16(dA + (s) * STG,      pA + (k0));          \
        cp16(dA + (s) * STG + 16, pA + (k0) + 8);      \
        cp16(dW + (s) * STG,      pW + (k0));          \
        cp16(dW + (s) * STG + 16, pW + (k0) + 8);      \
        cp_commit();                                   \
    } while (0)

    ISSUE(0, 0);
    ISSUE(1, 32);
    ISSUE(2, 64);

    float acc[4][4][4];                             // mt x nt x quad
    #pragma unroll
    for (int mt = 0; mt < 4; mt++)
        #pragma unroll
        for (int nt = 0; nt < 4; nt++)
            #pragma unroll
            for (int q = 0; q < 4; q++) acc[mt][nt][q] = 0.f;

    // per-lane LDSM row components (in halfs)
    int arow = lane & 15;
    int akoff = (lane >> 4) * 8;
    int brow = (lane & 7) + ((lane & 16) ? 8 : 0);
    int bkoff = (lane & 8) ? 8 : 0;
    uint32_t rowA[4], rowB[2];
    #pragma unroll
    for (int mt = 0; mt < 4; mt++)
        rowA[mt] = (uint32_t)((wm * 64 + mt * 16 + arow) * HST + akoff) * 2;
    #pragma unroll
    for (int ntp = 0; ntp < 2; ntp++)
        rowB[ntp] = (uint32_t)((wn * 32 + ntp * 16 + brow) * HST + bkoff) * 2;

    for (int i = 0; i < NIT; i++) {
        int s = i & (NSTAGE - 1);
        if (i + 2 < NIT) cp_wait<2>();
        else if (i + 1 < NIT) cp_wait<1>();
        else cp_wait<0>();
        __syncthreads();
        if (i + 3 < NIT) ISSUE((i + 3) & (NSTAGE - 1), (i + 3) * 32);

        uint32_t As = sb + s * STG;
        uint32_t Ws = As + A_PL;

        #pragma unroll
        for (int ks = 0; ks < 2; ks++) {
            uint32_t koff = (uint32_t)(ks * 16 * 2);
            uint32_t a[4][4], b[2][4];
            #pragma unroll
            for (int mt = 0; mt < 4; mt++)
                ldsm4(a[mt][0], a[mt][1], a[mt][2], a[mt][3], As + rowA[mt] + koff);
            #pragma unroll
            for (int ntp = 0; ntp < 2; ntp++)
                ldsm4(b[ntp][0], b[ntp][1], b[ntp][2], b[ntp][3], Ws + rowB[ntp] + koff);
            #pragma unroll
            for (int ntp = 0; ntp < 2; ntp++) {
                uint32_t bA[2] = { b[ntp][0], b[ntp][1] };
                uint32_t bB[2] = { b[ntp][2], b[ntp][3] };
                #pragma unroll
                for (int mt = 0; mt < 4; mt++) {
                    mma_f16(acc[mt][2 * ntp],     a[mt], bA);
                    mma_f16(acc[mt][2 * ntp + 1], a[mt], bB);
                }
            }
        }
    }
    #undef ISSUE

    // epilogue: warp covers rows wm*64..+63, cols wn*32..+31
    #pragma unroll
    for (int mt = 0; mt < 4; mt++) {
        int m0 = bm + wm * 64 + mt * 16 + lr;
        #pragma unroll
        for (int nt = 0; nt < 4; nt++) {
            int n = bn + wn * 32 + nt * 8 + lc * 2;
            if (WHICH == 1) {
                __half* C0 = g_xz + (size_t)m0 * NTOT + n;
                __half* C1 = g_xz + (size_t)(m0 + 8) * NTOT + n;
                *(__half2*)C0 = __halves2half2(__float2half_rn(acc[mt][nt][0]),
                                               __float2half_rn(acc[mt][nt][1]));
                *(__half2*)C1 = __halves2half2(__float2half_rn(acc[mt][nt][2]),
                                               __float2half_rn(acc[mt][nt][3]));
            } else {
                float* C0 = Cout + (size_t)m0 * NTOT + n;
                float* C1 = Cout + (size_t)(m0 + 8) * NTOT + n;
                const float2 r0 = *(const float2*)(R + (size_t)m0 * NTOT + n);
                const float2 r1 = *(const float2*)(R + (size_t)(m0 + 8) * NTOT + n);
                *(float2*)C0 = make_float2(acc[mt][nt][0] + r0.x, acc[mt][nt][1] + r0.y);
                *(float2*)C1 = make_float2(acc[mt][nt][2] + r1.x, acc[mt][nt][3] + r1.y);
            }
        }
    }
}

// ======== chunked parallel scan: y_t = alpha*y_{t-1} + conv(x)_t (reads fp16 xz) ====
__global__ void __launch_bounds__(256) scan_p1(const float* __restrict__ conv_w,
                                               const float* __restrict__ conv_b,
                                               const float* __restrict__ log_alpha) {
    int idx = blockIdx.x * 256 + threadIdx.x;
    int c = idx & (DI - 1);
    int j = (idx >> 11) & (NC - 1);
    int b = idx >> 17;
    float w0 = conv_w[c * 4 + 0], w1 = conv_w[c * 4 + 1];
    float w2 = conv_w[c * 4 + 2], w3 = conv_w[c * 4 + 3];
    float bias = conv_b[c];
    float alpha = 1.f / (1.f + __expf(-log_alpha[c / HD]));

    const __half* xp = g_xz + (size_t)b * Ss * (2 * DI) + c;
    int t0 = j * CL;
    float h0 = (t0 >= 3) ? __half2float(xp[(size_t)(t0 - 3) * (2 * DI)]) : 0.f;
    float h1 = (t0 >= 2) ? __half2float(xp[(size_t)(t0 - 2) * (2 * DI)]) : 0.f;
    float h2 = (t0 >= 1) ? __half2float(xp[(size_t)(t0 - 1) * (2 * DI)]) : 0.f;

    float e = 0.f;
    #pragma unroll 4
    for (int t = t0; t < t0 + CL; t++) {
        float xt = __half2float(xp[(size_t)t * (2 * DI)]);
        float cv = fmaf(w0, h0, fmaf(w1, h1, fmaf(w2, h2, fmaf(w3, xt, bias))));
        h0 = h1; h1 = h2; h2 = xt;
        e = fmaf(alpha, e, cv);
    }
    g_e[idx] = e;
}

__global__ void __launch_bounds__(256) scan_p2(const float* __restrict__ log_alpha) {
    int idx = blockIdx.x * 256 + threadIdx.x;
    int c = idx & (DI - 1);
    int b = idx >> 11;
    float alpha = 1.f / (1.f + __expf(-log_alpha[c / HD]));
    float aL = powf(alpha, (float)CL);
    float s = 0.f;
    size_t base = (size_t)b * NC * DI + c;
    #pragma unroll 8
    for (int j = 0; j < NC; j++) {
        g_s[base + (size_t)j * DI] = s;
        s = fmaf(aL, s, g_e[base + (size_t)j * DI]);
    }
}

__global__ void __launch_bounds__(256) scan_p3(const float* __restrict__ conv_w,
                                               const float* __restrict__ conv_b,
                                               const float* __restrict__ log_alpha) {
    int idx = blockIdx.x * 256 + threadIdx.x;
    int c = idx & (DI - 1);
    int j = (idx >> 11) & (NC - 1);
    int b = idx >> 17;
    float w0 = conv_w[c * 4 + 0], w1 = conv_w[c * 4 + 1];
    float w2 = conv_w[c * 4 + 2], w3 = conv_w[c * 4 + 3];
    float bias = conv_b[c];
    float alpha = 1.f / (1.f + __expf(-log_alpha[c / HD]));

    const __half* xp = g_xz + (size_t)b * Ss * (2 * DI) + c;
    const __half* gp = xp + DI;
    size_t ao = (size_t)b * Ss * DI + c;
    int t0 = j * CL;
    float h0 = (t0 >= 3) ? __half2float(xp[(size_t)(t0 - 3) * (2 * DI)]) : 0.f;
    float h1 = (t0 >= 2) ? __half2float(xp[(size_t)(t0 - 2) * (2 * DI)]) : 0.f;
    float h2 = (t0 >= 1) ? __half2float(xp[(size_t)(t0 - 1) * (2 * DI)]) : 0.f;

    float y = g_s[idx];
    #pragma unroll 4
    for (int t = t0; t < t0 + CL; t++) {
        float xt = __half2float(xp[(size_t)t * (2 * DI)]);
        float g  = __half2float(gp[(size_t)t * (2 * DI)]);
        float cv = fmaf(w0, h0, fmaf(w1, h1, fmaf(w2, h2, fmaf(w3, xt, bias))));
        h0 = h1; h1 = h2; h2 = xt;
        y = fmaf(alpha, y, cv);
        float sl = y * (1.f / (1.f + __expf(-y)));
        g_acth[ao + (size_t)t * DI] = __float2half_rn(sl * g);
    }
}

// ---------------- launch (NO device-symbol references in host code) ----------------
extern "C" void kernel_launch(void* const* d_in, const int* in_sizes, int n_in,
                              void* d_out, int out_size) {
    const float* x          = (const float*)d_in[0];
    const float* norm_w     = (const float*)d_in[1];
    const float* norm_b     = (const float*)d_in[2];
    const float* in_proj_w  = (const float*)d_in[3];
    const float* conv_w     = (const float*)d_in[4];
    const float* conv_b     = (const float*)d_in[5];
    const float* out_proj_w = (const float*)d_in[6];
    const float* log_alpha  = (const float*)d_in[7];
    float* out = (float*)d_out;

    cudaFuncSetAttribute(gemm_h<1>, cudaFuncAttributeMaxDynamicSharedMemorySize, GEMM_SMEM);
    cudaFuncSetAttribute(gemm_h<2>, cudaFuncAttributeMaxDynamicSharedMemorySize, GEMM_SMEM);

    int n1 = 2 * DI * Dd / 4, n2 = Dd * DI / 4;
    wprep<1><<<(n1 + 255) / 256, 256>>>(in_proj_w);
    wprep<2><<<(n2 + 255) / 256, 256>>>(out_proj_w);

    ln_kernel<<<Mm, 256>>>(x, norm_w, norm_b);

    dim3 g1((2 * DI) / 128, Mm / 128);           // (32, 128)
    gemm_h<1><<<g1, 256, GEMM_SMEM>>>(nullptr, nullptr);

    scan_p1<<<(Bb * NC * DI) / 256, 256>>>(conv_w, conv_b, log_alpha);
    scan_p2<<<(Bb * DI) / 256, 256>>>(log_alpha);
    scan_p3<<<(Bb * NC * DI) / 256, 256>>>(conv_w, conv_b, log_alpha);

    dim3 g2(Dd / 128, Mm / 128);                 // (8, 128)
    gemm_h<2><<<g2, 256, GEMM_SMEM>>>(x, out);
}